// round 1
// baseline (speedup 1.0000x reference)
#include <cuda_runtime.h>

// Problem constants (from reference):
//   N_UNIQUE=10000, N_BASES=10, FILTERS=16, B=32, L=100000
#define N_UNIQUE 10000
#define N_BASES  10
#define FILTERS  16
#define N_ELEMS  (32 * 100000)          // B*L
#define N_OUT4   (N_ELEMS * 4)          // output float4 count (16 floats = 4 float4 per elem)

// Scratch for the precomputed (bias-fused) unique-value table. Static device
// global — no allocation in kernel_launch (harness rule).
__device__ float4 g_shrunk4[N_UNIQUE * 4];   // [n_unique][16 floats] as float4[4]

// Kernel 1: shrunk_biased[u][f] = sum_b X_spline[u][b] * kernel[b][f] + bias[f]
// One thread per (u, f) scalar. 160K threads, trivially fast.
__global__ void precompute_shrunk(const float* __restrict__ X_spline,
                                  const float* __restrict__ kern,
                                  const float* __restrict__ bias) {
    int t = blockIdx.x * blockDim.x + threadIdx.x;
    if (t >= N_UNIQUE * FILTERS) return;
    int u = t >> 4;        // /FILTERS
    int f = t & 15;        // %FILTERS
    float acc = __ldg(bias + f);
#pragma unroll
    for (int b = 0; b < N_BASES; ++b) {
        acc = fmaf(__ldg(X_spline + u * N_BASES + b), __ldg(kern + b * FILTERS + f), acc);
    }
    reinterpret_cast<float*>(g_shrunk4)[t] = acc;
}

// Kernel 2: out[e][f] = shrunk_biased[idx[e]][f]
// One thread per output float4: thread i -> element e=i>>2, quarter j=i&3.
// idx load is broadcast among groups of 4 lanes; shrunk reads hit L2 (640 KB
// table); stores are perfectly coalesced 16B-per-lane.
__global__ __launch_bounds__(256) void gather_out(const int* __restrict__ idx,
                                                  float4* __restrict__ out4) {
    unsigned int i = blockIdx.x * 256u + threadIdx.x;
    if (i >= (unsigned int)N_OUT4) return;
    unsigned int e = i >> 2;
    unsigned int j = i & 3u;
    int u = __ldg(idx + e);
    out4[i] = g_shrunk4[(unsigned int)u * 4u + j];
}

extern "C" void kernel_launch(void* const* d_in, const int* in_sizes, int n_in,
                              void* d_out, int out_size) {
    // Identify inputs by element count (all distinct):
    //   idx: 3,200,000 (int32) | X_spline: 100,000 | kernel: 160 | bias: 16
    const int*   idx      = nullptr;
    const float* X_spline = nullptr;
    const float* kern     = nullptr;
    const float* bias     = nullptr;
    for (int i = 0; i < n_in; ++i) {
        switch (in_sizes[i]) {
            case N_ELEMS:             idx      = (const int*)  d_in[i]; break;
            case N_UNIQUE * N_BASES:  X_spline = (const float*)d_in[i]; break;
            case N_BASES * FILTERS:   kern     = (const float*)d_in[i]; break;
            case FILTERS:             bias     = (const float*)d_in[i]; break;
            default: break;
        }
    }

    // Kernel 1: tiny matmul + bias fuse into device scratch.
    {
        int total = N_UNIQUE * FILTERS;
        int threads = 256;
        int blocks = (total + threads - 1) / threads;
        precompute_shrunk<<<blocks, threads>>>(X_spline, kern, bias);
    }

    // Kernel 2: the memory-bound gather.
    {
        int threads = 256;
        int blocks = (N_OUT4 + threads - 1) / threads;
        gather_out<<<blocks, threads>>>(idx, (float4*)d_out);
    }
}

// round 2
// speedup vs baseline: 1.3646x; 1.3646x over previous
#include <cuda_runtime.h>

// Problem constants: N_UNIQUE=10000, N_BASES=10, FILTERS=16, B=32, L=100000
#define N_UNIQUE 10000
#define N_BASES  10
#define FILTERS  16
#define N_ELEMS  (32 * 100000)           // B*L = 3,200,000
#define N_OUT4   (N_ELEMS * 4)           // 12,800,000 float4 outputs
#define UNROLL   4
#define TPB      256
// N_OUT4 / (TPB*UNROLL) = 12,800,000 / 1024 = 12500 exactly — no tail.
#define GATHER_BLOCKS (N_OUT4 / (TPB * UNROLL))

// Precomputed bias-fused unique-value table (device global: allocation-free).
__device__ float4 g_shrunk4[N_UNIQUE * 4];   // [n_unique][16 floats] as 4x float4

// Kernel 1: shrunk_biased[u][f] = sum_b X_spline[u][b]*kernel[b][f] + bias[f]
__global__ void precompute_shrunk(const float* __restrict__ X_spline,
                                  const float* __restrict__ kern,
                                  const float* __restrict__ bias) {
    int t = blockIdx.x * blockDim.x + threadIdx.x;
    if (t >= N_UNIQUE * FILTERS) return;
    int u = t >> 4;
    int f = t & 15;
    float acc = __ldg(bias + f);
#pragma unroll
    for (int b = 0; b < N_BASES; ++b)
        acc = fmaf(__ldg(X_spline + u * N_BASES + b), __ldg(kern + b * FILTERS + f), acc);
    reinterpret_cast<float*>(g_shrunk4)[t] = acc;
}

// Kernel 2: out[e][f] = table[idx[e]][f], 4 independent chains per thread.
// Lane mapping: float4 slot i -> element e=i>>2, quarter j=i&3 => every load
// and store instruction is fully coalesced across the warp.
__global__ __launch_bounds__(TPB) void gather_out(const int* __restrict__ idx,
                                                  float4* __restrict__ out4) {
    const unsigned base = blockIdx.x * (TPB * UNROLL) + threadIdx.x;

    // Batch 1: independent idx loads (streaming — read exactly once).
    int u[UNROLL];
#pragma unroll
    for (int k = 0; k < UNROLL; ++k) {
        unsigned i = base + k * TPB;
        u[k] = __ldcs(idx + (i >> 2));
    }

    // Batch 2: independent table gathers (L2/L1-resident, keep cached).
    float4 v[UNROLL];
#pragma unroll
    for (int k = 0; k < UNROLL; ++k) {
        unsigned i = base + k * TPB;
        v[k] = __ldg(&g_shrunk4[(unsigned)u[k] * 4u + (i & 3u)]);
    }

    // Batch 3: streaming stores (write-once, evict-first).
#pragma unroll
    for (int k = 0; k < UNROLL; ++k) {
        unsigned i = base + k * TPB;
        __stcs(out4 + i, v[k]);
    }
}

extern "C" void kernel_launch(void* const* d_in, const int* in_sizes, int n_in,
                              void* d_out, int out_size) {
    // Identify inputs by element count (all distinct):
    // idx: 3,200,000 | X_spline: 100,000 | kernel: 160 | bias: 16
    const int*   idx      = nullptr;
    const float* X_spline = nullptr;
    const float* kern     = nullptr;
    const float* bias     = nullptr;
    for (int i = 0; i < n_in; ++i) {
        switch (in_sizes[i]) {
            case N_ELEMS:             idx      = (const int*)  d_in[i]; break;
            case N_UNIQUE * N_BASES:  X_spline = (const float*)d_in[i]; break;
            case N_BASES * FILTERS:   kern     = (const float*)d_in[i]; break;
            case FILTERS:             bias     = (const float*)d_in[i]; break;
            default: break;
        }
    }

    {
        int total = N_UNIQUE * FILTERS;
        precompute_shrunk<<<(total + TPB - 1) / TPB, TPB>>>(X_spline, kern, bias);
    }
    gather_out<<<GATHER_BLOCKS, TPB>>>(idx, (float4*)d_out);
}